// round 13
// baseline (speedup 1.0000x reference)
#include <cuda_runtime.h>
#include <cuda_fp16.h>
#include <cstdint>

#define NTOK 16384

// Scratch (allocation-free rule: __device__ globals)
__device__ __half g_xph[33554432];  // x @ W_in, fp16
__device__ __half g_wt1[65536];     // W_in^T  [n][k], fp16
__device__ __half g_wt2[65536];     // W_out^T [n][k], fp16

// ---------------------------------------------------------------------------
__device__ __forceinline__ uint32_t smem_u32(const void* p) {
    uint32_t a;
    asm("{ .reg .u64 t; cvta.to.shared.u64 t, %1; cvt.u32.u64 %0, t; }"
        : "=r"(a) : "l"(p));
    return a;
}
__device__ __forceinline__ void mma_fp16(float* d, const uint32_t* a,
                                         const uint32_t* b) {
    asm volatile(
        "mma.sync.aligned.m16n8k16.row.col.f32.f16.f16.f32 "
        "{%0,%1,%2,%3}, {%4,%5,%6,%7}, {%8,%9}, {%0,%1,%2,%3};"
        : "+f"(d[0]), "+f"(d[1]), "+f"(d[2]), "+f"(d[3])
        : "r"(a[0]), "r"(a[1]), "r"(a[2]), "r"(a[3]), "r"(b[0]), "r"(b[1]));
}
#define LDSM4(R0, R1, R2, R3, addr) \
    asm volatile("ldmatrix.sync.aligned.m8n8.x4.shared.b16 {%0,%1,%2,%3}, [%4];" \
                 : "=r"(R0), "=r"(R1), "=r"(R2), "=r"(R3) : "r"(addr))
#define CP_ASYNC16(dst, src) \
    asm volatile("cp.async.ca.shared.global [%0], [%1], 16;" \
                 :: "r"(dst), "l"(src))
#define CP_COMMIT() asm volatile("cp.async.commit_group;")
#define CP_WAIT0()  asm volatile("cp.async.wait_group 0;")
#define CP_WAIT1()  asm volatile("cp.async.wait_group 1;")

// ---------------------------------------------------------------------------
// Transpose + fp16 convert: Wt[n][k] = (half)W[k][n], 256x256
// ---------------------------------------------------------------------------
__global__ void transpose_half(const float* __restrict__ W,
                               __half* __restrict__ Wt)
{
    __shared__ float tile[32][33];
    const int bx = (blockIdx.x & 7) << 5;
    const int by = (blockIdx.x >> 3) << 5;
    const int tx = threadIdx.x & 31;
    const int ty = threadIdx.x >> 5;
#pragma unroll
    for (int i = 0; i < 32; i += 8)
        tile[ty + i][tx] = W[(by + ty + i) * 256 + bx + tx];
    __syncthreads();
#pragma unroll
    for (int i = 0; i < 32; i += 8)
        Wt[(bx + ty + i) * 256 + by + tx] = __float2half_rn(tile[tx][ty + i]);
}

// ---------------------------------------------------------------------------
// Stage-1 GEMM: xp(fp16) = x(fp32) @ W_in^T + b_in  (unchanged from R11)
// ---------------------------------------------------------------------------
#define SROW 80
#define OFF_A 0
#define OFF_B 10240
#define BUFB  20480
#define GEMM_SMEM (2 * BUFB)

__global__ __launch_bounds__(256) void gemm_f32in_f16out(
    const float* __restrict__ A, const __half* __restrict__ Bt,
    const float* __restrict__ bias, __half* __restrict__ C)
{
    extern __shared__ char sm[];
    const uint32_t smb = smem_u32(sm);
    const int t    = threadIdx.x;
    const int lane = t & 31;
    const int warp = t >> 5;
    const int wm0  = (warp >> 2) * 64;
    const int wn0  = (warp & 3) * 32;
    const int row0 = blockIdx.y << 7;
    const int col0 = blockIdx.x << 7;

    const int lr = t >> 3;
    const int lk = (t & 7) << 2;

    float acc[4][4][4];
#pragma unroll
    for (int i = 0; i < 4; i++)
#pragma unroll
        for (int j = 0; j < 4; j++)
#pragma unroll
            for (int k = 0; k < 4; k++) acc[i][j][k] = 0.f;

    float4 pa[4];
    uint2  pb[4];

    const uint32_t aoff = (uint32_t)(wm0 + (lane & 15)) * SROW + ((lane >> 4) << 4);
    const uint32_t boff = (uint32_t)(wn0 + (lane & 15)) * SROW + ((lane >> 4) << 4);

#define LOAD_CHUNK1(k0)                                                         \
    do {                                                                        \
        _Pragma("unroll")                                                       \
        for (int i = 0; i < 4; i++) {                                           \
            const int r = i * 32 + lr;                                          \
            pa[i] = *(const float4*)(A  + (size_t)(row0 + r) * 256 + (k0) + lk); \
            pb[i] = *(const uint2*)(Bt + (size_t)(col0 + r) * 256 + (k0) + lk); \
        }                                                                       \
    } while (0)

#define STORE_CHUNK1(bufoff)                                                    \
    do {                                                                        \
        char* base = sm + (bufoff);                                             \
        _Pragma("unroll")                                                       \
        for (int i = 0; i < 4; i++) {                                           \
            const int r = i * 32 + lr;                                          \
            const uint32_t off = (uint32_t)r * SROW + ((t & 7) << 3);           \
            uint2 hh;                                                           \
            __half2 h0 = __floats2half2_rn(pa[i].x, pa[i].y);                   \
            __half2 h1 = __floats2half2_rn(pa[i].z, pa[i].w);                   \
            hh.x = *(uint32_t*)&h0;                                             \
            hh.y = *(uint32_t*)&h1;                                             \
            *(uint2*)(base + OFF_A + off) = hh;                                 \
            *(uint2*)(base + OFF_B + off) = pb[i];                              \
        }                                                                       \
    } while (0)

    LOAD_CHUNK1(0);
    STORE_CHUNK1(0);
    __syncthreads();

    for (int c = 0; c < 8; c++) {
        const uint32_t cur = (uint32_t)(c & 1) * BUFB;
        const uint32_t nxt = BUFB - cur;
        if (c < 7) LOAD_CHUNK1((c + 1) * 32);

        const uint32_t AB = smb + cur + OFF_A;
        const uint32_t BB = smb + cur + OFF_B;

#pragma unroll
        for (int ks = 0; ks < 2; ks++) {
            const uint32_t kb = ks * 32;
            uint32_t ah[4][4], bf[4][2];
#pragma unroll
            for (int mf = 0; mf < 4; mf++)
                LDSM4(ah[mf][0], ah[mf][1], ah[mf][2], ah[mf][3],
                      AB + aoff + mf * (16 * SROW) + kb);
#pragma unroll
            for (int np = 0; np < 2; np++) {
                uint32_t r0, r1, r2, r3;
                LDSM4(r0, r1, r2, r3, BB + boff + np * (16 * SROW) + kb);
                bf[2 * np][0] = r0; bf[2 * np][1] = r2;
                bf[2 * np + 1][0] = r1; bf[2 * np + 1][1] = r3;
            }
#pragma unroll
            for (int mf = 0; mf < 4; mf++)
#pragma unroll
                for (int nf = 0; nf < 4; nf++)
                    mma_fp16(acc[mf][nf], ah[mf], bf[nf]);
        }

        if (c < 7) STORE_CHUNK1(nxt);
        __syncthreads();
    }

#pragma unroll
    for (int nf = 0; nf < 4; nf++) {
        const int cc = col0 + wn0 + nf * 8 + (lane & 3) * 2;
        const float b0 = bias[cc], b1 = bias[cc + 1];
#pragma unroll
        for (int mf = 0; mf < 4; mf++) {
            const int r = row0 + wm0 + mf * 16 + (lane >> 2);
            __half2 o0 = __floats2half2_rn(acc[mf][nf][0] + b0, acc[mf][nf][1] + b1);
            __half2 o1 = __floats2half2_rn(acc[mf][nf][2] + b0, acc[mf][nf][3] + b1);
            *(uint32_t*)(C + (size_t)r * 256 + cc) = *(uint32_t*)&o0;
            *(uint32_t*)(C + (size_t)(r + 8) * 256 + cc) = *(uint32_t*)&o1;
        }
    }
}

// ---------------------------------------------------------------------------
// FUSED attention + output GEMM. One CTA per (b,blk), 256 threads.
//   Phase 1: for 4 head-pairs: D_h(64x32) = A_h(64x80) @ X_h(80x32) -> yS smem
//   Phase 2: out(64x256) = yS(64x256) @ W_out^T(256x256) + bias -> global fp32
// ---------------------------------------------------------------------------
#define AH   88                     // halves per A row
#define AHB  176
#define YST  264                    // halves per yS row
#define YSTB 528
#define WROWB 48                    // W chunk: 16 halves + pad = 48 B per n-row
#define FUSED_SMEM (64 * YST * 2 + (2 * 64 * AH + 2 * 32 * AH) * 2)  // 67584

__global__ __launch_bounds__(256, 2) void attn_out_fused(
    const float* __restrict__ aw, const int* __restrict__ idx,
    const float* __restrict__ wsel, const __half* __restrict__ Wt,
    const float* __restrict__ bias, float* __restrict__ out)
{
    extern __shared__ __half smh[];
    __half* yS   = smh;                       // [64][YST]
    __half* sA0  = smh + 64 * YST;            // [64][AH]
    __half* sA1  = sA0 + 64 * AH;
    __half* sXT0 = sA1 + 64 * AH;             // [32][AH]
    __half* sXT1 = sXT0 + 32 * AH;

    const int t    = threadIdx.x;
    const int bid  = blockIdx.x;              // b*256 + blk
    const int blk  = bid & 255;
    const int b    = bid >> 8;
    const int bh   = blk >> 4;
    const int bw   = blk & 15;
    const int lane = t & 31;
    const int warp = t >> 5;
    const int g    = lane >> 2;
    const int tg   = lane & 3;

    const size_t xpb = (size_t)b * NTOK * 256;

    // ================= Phase 1: attention, 4 head-pair iterations ==========
    for (int it = 0; it < 4; it++) {
        const int h0 = it * 2;

        // stage A for heads h0, h0+1: 2x(64x80) fp32 -> fp16, 10 float4/thread
#pragma unroll
        for (int i = 0; i < 10; i++) {
            const int v  = i * 256 + t;
            const int hd = v >= 1280;
            const int u  = v - hd * 1280;
            const int q  = u / 20;
            const int m  = u % 20;
            const float* Ab = aw + ((size_t)(h0 + hd) * 2048 + bid) * 5120;
            const float4 a = *(const float4*)(Ab + q * 80 + m * 4);
            __half2 p0 = __floats2half2_rn(a.x, a.y);
            __half2 p1 = __floats2half2_rn(a.z, a.w);
            uint2 hv;
            hv.x = *(uint32_t*)&p0;
            hv.y = *(uint32_t*)&p1;
            __half* dst = hd ? sA1 : sA0;
            *(uint2*)(dst + q * AH + m * 4) = hv;
        }

        // stage X^T local tokens for both heads: 1024 uint2, 4/thread
#pragma unroll
        for (int i = 0; i < 4; i++) {
            const int v  = i * 256 + t;
            const int hd = v >= 512;
            const int u  = v & 511;
            const int p  = u >> 3;
            const int dq = u & 7;
            const int r  = p >> 3, c = p & 7;
            const int sp = (bh * 8 + r) * 128 + bw * 8 + c;
            const uint2 hv = *(const uint2*)(g_xph + xpb + (size_t)sp * 256 +
                                             (h0 + hd) * 32 + dq * 4);
            const __half2 x0 = *(const __half2*)&hv.x;
            const __half2 x1 = *(const __half2*)&hv.y;
            __half* X = hd ? sXT1 : sXT0;
            X[(dq * 4 + 0) * AH + p] = __low2half(x0);
            X[(dq * 4 + 1) * AH + p] = __high2half(x0);
            X[(dq * 4 + 2) * AH + p] = __low2half(x1);
            X[(dq * 4 + 3) * AH + p] = __high2half(x1);
        }
        // stage X^T selected tokens, weighted: 256 threads, 1 each
        {
            const int hd   = t >= 128;
            const int u    = t & 127;
            const int j    = u >> 3;
            const int dq   = u & 7;
            const int base = (b * 256 + blk) * 16 + j;
            const int tok  = idx[base];
            const float w  = wsel[base];
            const uint2 hv = *(const uint2*)(g_xph + xpb + (size_t)tok * 256 +
                                             (h0 + hd) * 32 + dq * 4);
            const float2 f0 = __half22float2(*(const __half2*)&hv.x);
            const float2 f1 = __half22float2(*(const __half2*)&hv.y);
            __half* X = hd ? sXT1 : sXT0;
            X[(dq * 4 + 0) * AH + 64 + j] = __float2half_rn(f0.x * w);
            X[(dq * 4 + 1) * AH + 64 + j] = __float2half_rn(f0.y * w);
            X[(dq * 4 + 2) * AH + 64 + j] = __float2half_rn(f1.x * w);
            X[(dq * 4 + 3) * AH + 64 + j] = __float2half_rn(f1.y * w);
        }
        __syncthreads();

        // MMA: warps 0-3 head h0, warps 4-7 head h0+1; 16 rows each
        {
            const int hd = warp >> 2;
            const int m0 = (warp & 3) << 4;
            const uint32_t aoff = smem_u32(hd ? sA1 : sA0) +
                                  (uint32_t)(m0 + (lane & 15)) * AHB +
                                  ((lane >> 4) << 4);
            const uint32_t boff = smem_u32(hd ? sXT1 : sXT0) +
                                  (uint32_t)(lane & 15) * AHB +
                                  ((lane >> 4) << 4);
            float acc[4][4];
#pragma unroll
            for (int i = 0; i < 4; i++)
#pragma unroll
                for (int j = 0; j < 4; j++) acc[i][j] = 0.f;

#pragma unroll
            for (int ks = 0; ks < 5; ks++) {
                const uint32_t kb = ks * 32;
                uint32_t ah[4], bf[4][2];
                LDSM4(ah[0], ah[1], ah[2], ah[3], aoff + kb);
#pragma unroll
                for (int np = 0; np < 2; np++) {
                    uint32_t r0, r1, r2, r3;
                    LDSM4(r0, r1, r2, r3, boff + np * (16 * AHB) + kb);
                    bf[2 * np][0] = r0; bf[2 * np][1] = r2;
                    bf[2 * np + 1][0] = r1; bf[2 * np + 1][1] = r3;
                }
#pragma unroll
                for (int nf = 0; nf < 4; nf++)
                    mma_fp16(acc[nf], ah, bf[nf]);
            }

            // write D tile into yS (fp16), cols (h0+hd)*32 + ...
            const int col0 = (h0 + hd) * 32;
#pragma unroll
            for (int nf = 0; nf < 4; nf++) {
#pragma unroll
                for (int hf = 0; hf < 2; hf++) {
                    const int q = m0 + g + hf * 8;
                    __half2 o = __floats2half2_rn(acc[nf][hf * 2 + 0],
                                                  acc[nf][hf * 2 + 1]);
                    *(uint32_t*)(yS + q * YST + col0 + nf * 8 + tg * 2) =
                        *(uint32_t*)&o;
                }
            }
        }
        __syncthreads();
    }

    // ================= Phase 2: out = yS @ W_out^T + bias ===================
    // Reuse A/XT stage area as double-buffered W chunks [256 n][16 k halves]
    const uint32_t wbb  = smem_u32(sA0);
    const int m0 = (warp & 3) << 4;        // token rows
    const int n0 = (warp >> 2) << 7;       // 0 or 128

    float acc[16][4];
#pragma unroll
    for (int i = 0; i < 16; i++)
#pragma unroll
        for (int j = 0; j < 4; j++) acc[i][j] = 0.f;

    const uint32_t aoy = smem_u32(yS) + (uint32_t)(m0 + (lane & 15)) * YSTB +
                         ((lane >> 4) << 4);

#define ASYNC_W(kc, buf)                                                       \
    do {                                                                       \
        CP_ASYNC16(wbb + (buf) * 12288 + t * WROWB,                            \
                   Wt + (size_t)t * 256 + (kc) * 16);                          \
        CP_ASYNC16(wbb + (buf) * 12288 + t * WROWB + 16,                       \
                   Wt + (size_t)t * 256 + (kc) * 16 + 8);                      \
        CP_COMMIT();                                                           \
    } while (0)

    ASYNC_W(0, 0);
    for (int kc = 0; kc < 16; kc++) {
        const int cur = kc & 1;
        if (kc < 15) {
            ASYNC_W(kc + 1, cur ^ 1);
            CP_WAIT1();
        } else {
            CP_WAIT0();
        }
        __syncthreads();   // chunk kc visible to all threads

        uint32_t ah[4];
        LDSM4(ah[0], ah[1], ah[2], ah[3], aoy + kc * 32);
#pragma unroll
        for (int np = 0; np < 8; np++) {
            uint32_t r0, r1, r2, r3;
            LDSM4(r0, r1, r2, r3,
                  wbb + cur * 12288 +
                  (uint32_t)(n0 + np * 16 + (lane & 15)) * WROWB +
                  ((lane >> 4) << 4));
            uint32_t bf0[2] = {r0, r2};
            uint32_t bf1[2] = {r1, r3};
            mma_fp16(acc[np * 2 + 0], ah, bf0);
            mma_fp16(acc[np * 2 + 1], ah, bf1);
        }
        __syncthreads();   // all consumed before buffer cur is overwritten
    }

    // epilogue: +bias, fp32 stores to final output
#pragma unroll
    for (int nf = 0; nf < 16; nf++) {
        const int cc = n0 + nf * 8 + tg * 2;
        const float b0 = bias[cc], b1 = bias[cc + 1];
#pragma unroll
        for (int hf = 0; hf < 2; hf++) {
            const int q  = m0 + g + hf * 8;
            const int r  = q >> 3, c = q & 7;
            const int sp = (bh * 8 + r) * 128 + bw * 8 + c;
            const float2 o = make_float2(acc[nf][hf * 2 + 0] + b0,
                                         acc[nf][hf * 2 + 1] + b1);
            *(float2*)(out + ((size_t)b * NTOK + sp) * 256 + cc) = o;
        }
    }
}

// ===========================================================================
extern "C" void kernel_launch(void* const* d_in, const int* in_sizes, int n_in,
                              void* d_out, int out_size)
{
    const float* x    = (const float*)d_in[0];
    const float* aw   = (const float*)d_in[1];
    const int*   idx  = (const int*)d_in[2];
    const float* wsel = (const float*)d_in[3];
    const float* Win  = (const float*)d_in[4];
    const float* bin  = (const float*)d_in[5];
    const float* Wout = (const float*)d_in[6];
    const float* bout = (const float*)d_in[7];
    float* out = (float*)d_out;

    __half *xph, *wt1, *wt2;
    cudaGetSymbolAddress((void**)&xph, g_xph);
    cudaGetSymbolAddress((void**)&wt1, g_wt1);
    cudaGetSymbolAddress((void**)&wt2, g_wt2);

    cudaFuncSetAttribute(gemm_f32in_f16out,
                         cudaFuncAttributeMaxDynamicSharedMemorySize, GEMM_SMEM);
    cudaFuncSetAttribute(attn_out_fused,
                         cudaFuncAttributeMaxDynamicSharedMemorySize, FUSED_SMEM);

    transpose_half<<<64, 256>>>(Win, wt1);
    transpose_half<<<64, 256>>>(Wout, wt2);

    gemm_f32in_f16out<<<dim3(2, 1024), 256, GEMM_SMEM>>>(x, wt1, bin, xph);
    attn_out_fused<<<2048, 256, FUSED_SMEM>>>(aw, idx, wsel, wt2, bout, out);
}

// round 14
// speedup vs baseline: 1.1921x; 1.1921x over previous
#include <cuda_runtime.h>
#include <cuda_fp16.h>
#include <cstdint>

#define NTOK 16384

// Scratch (allocation-free rule: __device__ globals)
__device__ __half g_xph[33554432];  // x @ W_in, fp16
__device__ __half g_yh[33554432];   // attention output, fp16
__device__ __half g_wt1[65536];     // W_in^T  [n][k], fp16
__device__ __half g_wt2[65536];     // W_out^T [n][k], fp16

// ---------------------------------------------------------------------------
__device__ __forceinline__ uint32_t smem_u32(const void* p) {
    uint32_t a;
    asm("{ .reg .u64 t; cvta.to.shared.u64 t, %1; cvt.u32.u64 %0, t; }"
        : "=r"(a) : "l"(p));
    return a;
}
__device__ __forceinline__ void mma_fp16(float* d, const uint32_t* a,
                                         const uint32_t* b) {
    asm volatile(
        "mma.sync.aligned.m16n8k16.row.col.f32.f16.f16.f32 "
        "{%0,%1,%2,%3}, {%4,%5,%6,%7}, {%8,%9}, {%0,%1,%2,%3};"
        : "+f"(d[0]), "+f"(d[1]), "+f"(d[2]), "+f"(d[3])
        : "r"(a[0]), "r"(a[1]), "r"(a[2]), "r"(a[3]), "r"(b[0]), "r"(b[1]));
}
#define LDSM4(R0, R1, R2, R3, addr) \
    asm volatile("ldmatrix.sync.aligned.m8n8.x4.shared.b16 {%0,%1,%2,%3}, [%4];" \
                 : "=r"(R0), "=r"(R1), "=r"(R2), "=r"(R3) : "r"(addr))
#define CP_ASYNC16(dst, src) \
    asm volatile("cp.async.ca.shared.global [%0], [%1], 16;" \
                 :: "r"(dst), "l"(src))
#define CP_COMMIT() asm volatile("cp.async.commit_group;")
#define CP_WAIT0()  asm volatile("cp.async.wait_group 0;")

// ---------------------------------------------------------------------------
// Merged transpose + fp16 convert for both weight matrices.
//   blocks 0..63: wt1 = Win^T; blocks 64..127: wt2 = Wout^T
// ---------------------------------------------------------------------------
__global__ void transpose_both(const float* __restrict__ W1,
                               __half* __restrict__ T1,
                               const float* __restrict__ W2,
                               __half* __restrict__ T2)
{
    __shared__ float tile[32][33];
    const int sel = blockIdx.x >> 6;
    const int bb  = blockIdx.x & 63;
    const float* W = sel ? W2 : W1;
    __half*      T = sel ? T2 : T1;
    const int bx = (bb & 7) << 5;
    const int by = (bb >> 3) << 5;
    const int tx = threadIdx.x & 31;
    const int ty = threadIdx.x >> 5;
#pragma unroll
    for (int i = 0; i < 32; i += 8)
        tile[ty + i][tx] = W[(by + ty + i) * 256 + bx + tx];
    __syncthreads();
#pragma unroll
    for (int i = 0; i < 32; i += 8)
        T[(bx + ty + i) * 256 + by + tx] = __float2half_rn(tile[tx][ty + i]);
}

// ---------------------------------------------------------------------------
// GEMM common geometry: CTA 128x128, BK=32, 256 thr, 8 warps (2M x 4N)
// ---------------------------------------------------------------------------
#define SROW 80                    // bytes per smem row (32 fp16 + 8 pad)
#define OFF_A 0
#define OFF_B 10240
#define BUFB  20480
#define GEMM_SMEM (2 * BUFB)       // 40960

// === Variant 1: A fp32 in (reg path + cvt), B fp16 cp.async, C fp16 out ====
__global__ __launch_bounds__(256) void gemm_f32in_f16out(
    const float* __restrict__ A, const __half* __restrict__ Bt,
    const float* __restrict__ bias, __half* __restrict__ C)
{
    extern __shared__ char sm[];
    const uint32_t smb = smem_u32(sm);
    const int t    = threadIdx.x;
    const int lane = t & 31;
    const int warp = t >> 5;
    const int wm0  = (warp >> 2) * 64;
    const int wn0  = (warp & 3) * 32;
    const int row0 = blockIdx.y << 7;
    const int col0 = blockIdx.x << 7;

    const int lr = t >> 3;          // A map: rows i*32+lr
    const int lk = (t & 7) << 2;    // A k-offset (4 floats)
    const int cr = t >> 2;          // B cp.async map: rows i*64+cr
    const int cs = t & 3;           // 16B segment

    float acc[4][4][4];
#pragma unroll
    for (int i = 0; i < 4; i++)
#pragma unroll
        for (int j = 0; j < 4; j++)
#pragma unroll
            for (int k = 0; k < 4; k++) acc[i][j][k] = 0.f;

    float4 pa[4];

    const uint32_t aoff = (uint32_t)(wm0 + (lane & 15)) * SROW + ((lane >> 4) << 4);
    const uint32_t boff = (uint32_t)(wn0 + (lane & 15)) * SROW + ((lane >> 4) << 4);

#define B_ASYNC1(k0, bufoff)                                                    \
    do {                                                                        \
        _Pragma("unroll")                                                       \
        for (int i = 0; i < 2; i++) {                                           \
            const int r = i * 64 + cr;                                          \
            CP_ASYNC16(smb + (bufoff) + OFF_B + (uint32_t)r * SROW + cs * 16,   \
                       Bt + (size_t)(col0 + r) * 256 + (k0) + cs * 8);          \
        }                                                                       \
        CP_COMMIT();                                                            \
    } while (0)

#define A_LOAD1(k0)                                                             \
    do {                                                                        \
        _Pragma("unroll")                                                       \
        for (int i = 0; i < 4; i++)                                             \
            pa[i] = *(const float4*)(A + (size_t)(row0 + i * 32 + lr) * 256 +   \
                                     (k0) + lk);                                \
    } while (0)

#define A_STORE1(bufoff)                                                        \
    do {                                                                        \
        char* base = sm + (bufoff);                                             \
        _Pragma("unroll")                                                       \
        for (int i = 0; i < 4; i++) {                                           \
            const int r = i * 32 + lr;                                          \
            const uint32_t off = (uint32_t)r * SROW + ((t & 7) << 3);           \
            uint2 hh;                                                           \
            __half2 h0 = __floats2half2_rn(pa[i].x, pa[i].y);                   \
            __half2 h1 = __floats2half2_rn(pa[i].z, pa[i].w);                   \
            hh.x = *(uint32_t*)&h0;                                             \
            hh.y = *(uint32_t*)&h1;                                             \
            *(uint2*)(base + OFF_A + off) = hh;                                 \
        }                                                                       \
    } while (0)

    A_LOAD1(0);
    B_ASYNC1(0, 0);
    A_STORE1(0);
    CP_WAIT0();
    __syncthreads();

    for (int c = 0; c < 8; c++) {
        const uint32_t cur = (uint32_t)(c & 1) * BUFB;
        const uint32_t nxt = BUFB - cur;
        if (c < 7) {
            B_ASYNC1((c + 1) * 32, nxt);
            A_LOAD1((c + 1) * 32);
        }

        const uint32_t AB = smb + cur + OFF_A;
        const uint32_t BB = smb + cur + OFF_B;

#pragma unroll
        for (int ks = 0; ks < 2; ks++) {
            const uint32_t kb = ks * 32;
            uint32_t ah[4][4], bf[4][2];
#pragma unroll
            for (int mf = 0; mf < 4; mf++)
                LDSM4(ah[mf][0], ah[mf][1], ah[mf][2], ah[mf][3],
                      AB + aoff + mf * (16 * SROW) + kb);
#pragma unroll
            for (int np = 0; np < 2; np++) {
                uint32_t r0, r1, r2, r3;
                LDSM4(r0, r1, r2, r3, BB + boff + np * (16 * SROW) + kb);
                bf[2 * np][0] = r0; bf[2 * np][1] = r2;
                bf[2 * np + 1][0] = r1; bf[2 * np + 1][1] = r3;
            }
#pragma unroll
            for (int mf = 0; mf < 4; mf++)
#pragma unroll
                for (int nf = 0; nf < 4; nf++)
                    mma_fp16(acc[mf][nf], ah[mf], bf[nf]);
        }

        if (c < 7) {
            A_STORE1(nxt);
            CP_WAIT0();
        }
        __syncthreads();
    }

    // Epilogue: +bias, fp16 stores
#pragma unroll
    for (int nf = 0; nf < 4; nf++) {
        const int cc = col0 + wn0 + nf * 8 + (lane & 3) * 2;
        const float b0 = bias[cc], b1 = bias[cc + 1];
#pragma unroll
        for (int mf = 0; mf < 4; mf++) {
            const int r = row0 + wm0 + mf * 16 + (lane >> 2);
            __half2 o0 = __floats2half2_rn(acc[mf][nf][0] + b0, acc[mf][nf][1] + b1);
            __half2 o1 = __floats2half2_rn(acc[mf][nf][2] + b0, acc[mf][nf][3] + b1);
            *(uint32_t*)(C + (size_t)r * 256 + cc) = *(uint32_t*)&o0;
            *(uint32_t*)(C + (size_t)(r + 8) * 256 + cc) = *(uint32_t*)&o1;
        }
    }
}

// === Variant 2: A fp16 in (cp.async both operands), C fp32 out (stage 3) ===
__global__ __launch_bounds__(256) void gemm_f16in_f32out(
    const __half* __restrict__ A, const __half* __restrict__ Bt,
    const float* __restrict__ bias, float* __restrict__ C)
{
    extern __shared__ char sm[];
    const uint32_t smb = smem_u32(sm);
    const int t    = threadIdx.x;
    const int lane = t & 31;
    const int warp = t >> 5;
    const int wm0  = (warp >> 2) * 64;
    const int wn0  = (warp & 3) * 32;
    const int row0 = blockIdx.y << 7;
    const int col0 = blockIdx.x << 7;

    const int cr = t >> 2;
    const int cs = t & 3;

    float acc[4][4][4];
#pragma unroll
    for (int i = 0; i < 4; i++)
#pragma unroll
        for (int j = 0; j < 4; j++)
#pragma unroll
            for (int k = 0; k < 4; k++) acc[i][j][k] = 0.f;

    const uint32_t aoff = (uint32_t)(wm0 + (lane & 15)) * SROW + ((lane >> 4) << 4);
    const uint32_t boff = (uint32_t)(wn0 + (lane & 15)) * SROW + ((lane >> 4) << 4);

#define ASYNC_CHUNK2(k0, bufoff)                                                \
    do {                                                                        \
        _Pragma("unroll")                                                       \
        for (int i = 0; i < 2; i++) {                                           \
            const int r = i * 64 + cr;                                          \
            const uint32_t off = (uint32_t)r * SROW + cs * 16;                  \
            CP_ASYNC16(smb + (bufoff) + OFF_A + off,                            \
                       A + (size_t)(row0 + r) * 256 + (k0) + cs * 8);           \
            CP_ASYNC16(smb + (bufoff) + OFF_B + off,                            \
                       Bt + (size_t)(col0 + r) * 256 + (k0) + cs * 8);          \
        }                                                                       \
        CP_COMMIT();                                                            \
    } while (0)

    ASYNC_CHUNK2(0, 0);
    CP_WAIT0();
    __syncthreads();

    for (int c = 0; c < 8; c++) {
        const uint32_t cur = (uint32_t)(c & 1) * BUFB;
        const uint32_t nxt = BUFB - cur;
        if (c < 7) ASYNC_CHUNK2((c + 1) * 32, nxt);

        const uint32_t AB = smb + cur + OFF_A;
        const uint32_t BB = smb + cur + OFF_B;

#pragma unroll
        for (int ks = 0; ks < 2; ks++) {
            const uint32_t kb = ks * 32;
            uint32_t ah[4][4], bf[4][2];
#pragma unroll
            for (int mf = 0; mf < 4; mf++)
                LDSM4(ah[mf][0], ah[mf][1], ah[mf][2], ah[mf][3],
                      AB + aoff + mf * (16 * SROW) + kb);
#pragma unroll
            for (int np = 0; np < 2; np++) {
                uint32_t r0, r1, r2, r3;
                LDSM4(r0, r1, r2, r3, BB + boff + np * (16 * SROW) + kb);
                bf[2 * np][0] = r0; bf[2 * np][1] = r2;
                bf[2 * np + 1][0] = r1; bf[2 * np + 1][1] = r3;
            }
#pragma unroll
            for (int mf = 0; mf < 4; mf++)
#pragma unroll
                for (int nf = 0; nf < 4; nf++)
                    mma_fp16(acc[mf][nf], ah[mf], bf[nf]);
        }

        if (c < 7) CP_WAIT0();
        __syncthreads();
    }

    // Epilogue: +bias, fp32 stores
#pragma unroll
    for (int nf = 0; nf < 4; nf++) {
        const int cc = col0 + wn0 + nf * 8 + (lane & 3) * 2;
        const float b0 = bias[cc], b1 = bias[cc + 1];
#pragma unroll
        for (int mf = 0; mf < 4; mf++) {
            const int r = row0 + wm0 + mf * 16 + (lane >> 2);
            float2 o0 = make_float2(acc[mf][nf][0] + b0, acc[mf][nf][1] + b1);
            float2 o1 = make_float2(acc[mf][nf][2] + b0, acc[mf][nf][3] + b1);
            *(float2*)(C + (size_t)r * 256 + cc) = o0;
            *(float2*)(C + (size_t)(r + 8) * 256 + cc) = o1;
        }
    }
}

// ---------------------------------------------------------------------------
// FP16-MMA attention (R11 structure, occupancy raised to 10 CTAs/SM).
//   D(64x32) = A(64x80) @ X(80x32) per (h,b,blk).
// ---------------------------------------------------------------------------
#define HROW 88                    // halves per row
#define HROWB (HROW * 2)           // 176 bytes

__global__ __launch_bounds__(128, 10) void attn_mma(const float* __restrict__ aw,
                                                    const int*   __restrict__ idx,
                                                    const float* __restrict__ wsel)
{
    __shared__ __half sA[64 * HROW];    // A[q][k]
    __shared__ __half sXT[32 * HROW];   // X^T[ch][tok]

    const int t    = threadIdx.x;
    const int bid  = blockIdx.x;
    const int blk  = bid & 255;
    const int b    = (bid >> 8) & 7;
    const int h    = bid >> 11;
    const int bh   = blk >> 4;
    const int bw   = blk & 15;
    const int lane = t & 31;
    const int warp = t >> 5;

    const uint32_t sAb  = smem_u32(sA);
    const uint32_t sXTb = smem_u32(sXT);

    // ---- stage A (64x80): coalesced float4 LDG, 10/thread, cvt to fp16
    const float* Ab = aw + (size_t)bid * 5120;
#pragma unroll
    for (int i = 0; i < 10; i++) {
        const int v = i * 128 + t;
        const int q = v / 20;
        const int m = v % 20;
        const float4 a = *(const float4*)(Ab + q * 80 + m * 4);
        __half2 h0 = __floats2half2_rn(a.x, a.y);
        __half2 h1 = __floats2half2_rn(a.z, a.w);
        uint2 hv;
        hv.x = *(uint32_t*)&h0;
        hv.y = *(uint32_t*)&h1;
        *(uint2*)(sA + q * HROW + m * 4) = hv;
    }

    const size_t xbase = (size_t)b * NTOK * 256 + h * 32;

    // ---- stage X^T: local 64 tokens (fp16 uint2 loads), transposed stores
#pragma unroll
    for (int i = 0; i < 4; i++) {
        const int v  = i * 128 + t;
        const int p  = v >> 3;          // token 0..63
        const int dq = v & 7;           // quad of 4 halves
        const int r  = p >> 3, c = p & 7;
        const int sp = (bh * 8 + r) * 128 + bw * 8 + c;
        const uint2 hv = *(const uint2*)(g_xph + xbase + (size_t)sp * 256 + dq * 4);
        const __half2 h0 = *(const __half2*)&hv.x;
        const __half2 h1 = *(const __half2*)&hv.y;
        sXT[(dq * 4 + 0) * HROW + p] = __low2half(h0);
        sXT[(dq * 4 + 1) * HROW + p] = __high2half(h0);
        sXT[(dq * 4 + 2) * HROW + p] = __low2half(h1);
        sXT[(dq * 4 + 3) * HROW + p] = __high2half(h1);
    }
    // ---- stage X^T: selected 16 tokens, weighted (fp32 mul, fp16 round)
    {
        const int j    = t >> 3;
        const int dq   = t & 7;
        const int base = (b * 256 + blk) * 16 + j;
        const int tok  = idx[base];
        const float w  = wsel[base];
        const uint2 hv = *(const uint2*)(g_xph + xbase + (size_t)tok * 256 + dq * 4);
        const float2 f0 = __half22float2(*(const __half2*)&hv.x);
        const float2 f1 = __half22float2(*(const __half2*)&hv.y);
        sXT[(dq * 4 + 0) * HROW + 64 + j] = __float2half_rn(f0.x * w);
        sXT[(dq * 4 + 1) * HROW + 64 + j] = __float2half_rn(f0.y * w);
        sXT[(dq * 4 + 2) * HROW + 64 + j] = __float2half_rn(f1.x * w);
        sXT[(dq * 4 + 3) * HROW + 64 + j] = __float2half_rn(f1.y * w);
    }
    __syncthreads();

    // ---- MMA: warp handles rows [m0, m0+16); 5 k16-steps x 4 n8-tiles
    const int m0 = warp << 4;
    const uint32_t aoff = sAb  + (uint32_t)(m0 + (lane & 15)) * HROWB +
                          ((lane >> 4) << 4);
    const uint32_t boff = sXTb + (uint32_t)(lane & 15) * HROWB +
                          ((lane >> 4) << 4);

    float acc[4][4];
#pragma unroll
    for (int i = 0; i < 4; i++)
#pragma unroll
        for (int j = 0; j < 4; j++) acc[i][j] = 0.f;

#pragma unroll
    for (int ks = 0; ks < 5; ks++) {
        const uint32_t kb = ks * 32;
        uint32_t ah[4], bf[4][2];
        LDSM4(ah[0], ah[1], ah[2], ah[3], aoff + kb);
#pragma unroll
        for (int np = 0; np < 2; np++) {
            uint32_t r0, r1, r2, r3;
            LDSM4(r0, r1, r2, r3, boff + np * (16 * HROWB) + kb);
            bf[2 * np][0] = r0; bf[2 * np][1] = r2;
            bf[2 * np + 1][0] = r1; bf[2 * np + 1][1] = r3;
        }
#pragma unroll
        for (int nf = 0; nf < 4; nf++)
            mma_fp16(acc[nf], ah, bf[nf]);
    }

    // ---- scatter D (fp16) to token-major y
    const int g  = lane >> 2;
    const int tg = lane & 3;
#pragma unroll
    for (int nf = 0; nf < 4; nf++) {
#pragma unroll
        for (int half = 0; half < 2; half++) {
            const int q  = m0 + g + half * 8;
            const int r  = q >> 3, c = q & 7;
            const int sp = (bh * 8 + r) * 128 + bw * 8 + c;
            __half2 o = __floats2half2_rn(acc[nf][half * 2 + 0],
                                          acc[nf][half * 2 + 1]);
            *(uint32_t*)(g_yh + xbase + (size_t)sp * 256 + nf * 8 + tg * 2) =
                *(uint32_t*)&o;
        }
    }
}

// ===========================================================================
extern "C" void kernel_launch(void* const* d_in, const int* in_sizes, int n_in,
                              void* d_out, int out_size)
{
    const float* x    = (const float*)d_in[0];
    const float* aw   = (const float*)d_in[1];
    const int*   idx  = (const int*)d_in[2];
    const float* wsel = (const float*)d_in[3];
    const float* Win  = (const float*)d_in[4];
    const float* bin  = (const float*)d_in[5];
    const float* Wout = (const float*)d_in[6];
    const float* bout = (const float*)d_in[7];
    float* out = (float*)d_out;

    __half *xph, *yh, *wt1, *wt2;
    cudaGetSymbolAddress((void**)&xph, g_xph);
    cudaGetSymbolAddress((void**)&yh, g_yh);
    cudaGetSymbolAddress((void**)&wt1, g_wt1);
    cudaGetSymbolAddress((void**)&wt2, g_wt2);

    cudaFuncSetAttribute(gemm_f32in_f16out,
                         cudaFuncAttributeMaxDynamicSharedMemorySize, GEMM_SMEM);
    cudaFuncSetAttribute(gemm_f16in_f32out,
                         cudaFuncAttributeMaxDynamicSharedMemorySize, GEMM_SMEM);

    transpose_both<<<128, 256>>>(Win, wt1, Wout, wt2);

    gemm_f32in_f16out<<<dim3(2, 1024), 256, GEMM_SMEM>>>(x, wt1, bin, xph);
    attn_mma<<<16384, 128>>>(aw, idx, wsel);
    gemm_f16in_f32out<<<dim3(2, 1024), 256, GEMM_SMEM>>>(yh, wt2, bout, out);
}